// round 2
// baseline (speedup 1.0000x reference)
#include <cuda_runtime.h>

#define Nn 50000
#define INd 128
#define Hh 4
#define Ff 32
#define Ee 500000
#define Ll 512
#define SLOPE 0.2f

// ---------------- device scratch (static, allocation-free) ----------------
__device__ __align__(16) float    g_fs[Nn * INd];          // feat_src (N,128)
__device__ __align__(16) float    g_fd[Nn * INd];          // feat_dst (N,128)
__device__ __align__(16) float    g_ex[2][Ee * Hh];        // logits -> exp values
__device__               unsigned g_segmax[2][Nn * Hh];    // encoded-float max
__device__               float    g_segsum[2][Nn * Hh];    // softmax denom
__device__ __align__(16) float    g_acc[Nn * INd];         // ft_p + ft_s
__device__ __align__(16) float    g_yh[Nn * Ll];           // label accumulation
__device__               int      g_flag_fmt;              // 0=int32, 1=uint8, 2=float32

// orderable-uint encoding of float for atomicMax
__device__ __forceinline__ unsigned encf(float f) {
    unsigned u = __float_as_uint(f);
    return (u & 0x80000000u) ? ~u : (u | 0x80000000u);
}
__device__ __forceinline__ float decf(unsigned u) {
    return (u & 0x80000000u) ? __uint_as_float(u ^ 0x80000000u)
                             : __uint_as_float(~u);
}

// vectorized global reduction (PTX ISA 8.3+, sm_90+)
__device__ __forceinline__ void red_add_v4(float* p, float a, float b, float c, float d) {
    asm volatile("red.global.add.v4.f32 [%0], {%1, %2, %3, %4};"
                 :: "l"(p), "f"(a), "f"(b), "f"(c), "f"(d) : "memory");
}

// ---------------- flag format detection (single block, deterministic) ----------------
__global__ void k_flagfmt(const unsigned* __restrict__ p) {
    __shared__ int s_word_not01, s_byte_not01;
    if (threadIdx.x == 0) { s_word_not01 = 0; s_byte_not01 = 0; }
    __syncthreads();
    const int nwords = Nn / 4;  // if int32 storage, first Nn words are flags; checking Nn/4 is enough either way
    int w_bad = 0, b_bad = 0;
    for (int i = threadIdx.x; i < nwords; i += blockDim.x) {
        unsigned w = p[i];
        if (w > 1u) w_bad = 1;
        unsigned b0 = w & 0xFFu, b1 = (w >> 8) & 0xFFu, b2 = (w >> 16) & 0xFFu, b3 = (w >> 24) & 0xFFu;
        if (b0 > 1u || b1 > 1u || b2 > 1u || b3 > 1u) b_bad = 1;
    }
    if (w_bad) atomicOr(&s_word_not01, 1);
    if (b_bad) atomicOr(&s_byte_not01, 1);
    __syncthreads();
    if (threadIdx.x == 0) {
        int fmt;
        if (!s_word_not01) fmt = 0;        // all words 0/1 -> int32 flags
        else if (!s_byte_not01) fmt = 1;   // bytes 0/1 -> uint8 flags
        else fmt = 2;                      // float32 flags (0.0 / 1.0)
        g_flag_fmt = fmt;
    }
}

// ---------------- init: zero accumulators ----------------
__global__ void k_init() {
    int tid = blockIdx.x * blockDim.x + threadIdx.x;
    int stride = gridDim.x * blockDim.x;
    float4 z4 = make_float4(0.f, 0.f, 0.f, 0.f);
    float4* yh4 = (float4*)g_yh;
    const int nyh = Nn * Ll / 4;
    for (int i = tid; i < nyh; i += stride) yh4[i] = z4;
    float4* ac4 = (float4*)g_acc;
    const int nac = Nn * INd / 4;
    for (int i = tid; i < nac; i += stride) ac4[i] = z4;
    unsigned* sm = (unsigned*)g_segmax;
    float* ss = (float*)g_segsum;
    const int nseg = 2 * Nn * Hh;
    for (int i = tid; i < nseg; i += stride) { sm[i] = 0u; ss[i] = 0.f; }
}

// ---------------- projection: fs = x W_src^T + b_src ; fd likewise ----------------
#define BR 16
__global__ void k_proj(const float* __restrict__ x,
                       const float* __restrict__ Ws, const float* __restrict__ bs,
                       const float* __restrict__ Wd, const float* __restrict__ bd) {
    __shared__ float xs[BR][INd];
    const int row0 = blockIdx.x * BR;
    for (int i = threadIdx.x; i < BR * INd; i += blockDim.x) {
        int r = i / INd, c = i % INd;
        xs[r][c] = x[(row0 + r) * INd + c];
    }
    __syncthreads();
    const int col = threadIdx.x; // 128 threads = 128 output columns
    float accS[BR], accD[BR];
#pragma unroll
    for (int r = 0; r < BR; r++) { accS[r] = 0.f; accD[r] = 0.f; }
    const float* wsr = Ws + col * INd;
    const float* wdr = Wd + col * INd;
    for (int k = 0; k < INd; k++) {
        float ws = __ldg(wsr + k);
        float wd = __ldg(wdr + k);
#pragma unroll
        for (int r = 0; r < BR; r++) {
            float xv = xs[r][k];
            accS[r] += xv * ws;
            accD[r] += xv * wd;
        }
    }
    float bsv = bs[col], bdv = bd[col];
#pragma unroll
    for (int r = 0; r < BR; r++) {
        g_fs[(row0 + r) * INd + col] = accS[r] + bsv;
        g_fd[(row0 + r) * INd + col] = accD[r] + bdv;
    }
}

// ---------------- edge logits + segment max (warp per edge) ----------------
__global__ void k_logits(const int* __restrict__ src, const int* __restrict__ dst,
                         const float* __restrict__ attn, int g) {
    const int warp = threadIdx.x >> 5;
    const int lane = threadIdx.x & 31;
    const int e = blockIdx.x * (blockDim.x >> 5) + warp;
    if (e >= Ee) return;
    const int s = src[e];
    const int d = dst[e];
    const float* pfs = g_fs + s * INd;
    const float* pfd = g_fd + d * INd;
    float a0, a1, a2, a3;
    {
        float v;
        v = pfs[lane] + pfd[lane];             v = v > 0.f ? v : SLOPE * v; a0 = v * attn[lane];
        v = pfs[32 + lane] + pfd[32 + lane];   v = v > 0.f ? v : SLOPE * v; a1 = v * attn[32 + lane];
        v = pfs[64 + lane] + pfd[64 + lane];   v = v > 0.f ? v : SLOPE * v; a2 = v * attn[64 + lane];
        v = pfs[96 + lane] + pfd[96 + lane];   v = v > 0.f ? v : SLOPE * v; a3 = v * attn[96 + lane];
    }
#pragma unroll
    for (int o = 16; o; o >>= 1) {
        a0 += __shfl_xor_sync(0xFFFFFFFFu, a0, o);
        a1 += __shfl_xor_sync(0xFFFFFFFFu, a1, o);
        a2 += __shfl_xor_sync(0xFFFFFFFFu, a2, o);
        a3 += __shfl_xor_sync(0xFFFFFFFFu, a3, o);
    }
    if (lane == 0) {
        float* lg = g_ex[g] + e * Hh;
        lg[0] = a0; lg[1] = a1; lg[2] = a2; lg[3] = a3;
        unsigned* sm = g_segmax[g] + d * Hh;
        atomicMax(&sm[0], encf(a0));
        atomicMax(&sm[1], encf(a1));
        atomicMax(&sm[2], encf(a2));
        atomicMax(&sm[3], encf(a3));
    }
}

// ---------------- exp + segment sum ----------------
__global__ void k_exp(const int* __restrict__ dst, int g) {
    int i = blockIdx.x * blockDim.x + threadIdx.x;
    if (i >= Ee * Hh) return;
    int e = i >> 2;
    int h = i & 3;
    int d = dst[e];
    float m = decf(g_segmax[g][d * Hh + h]);
    float v = expf(g_ex[g][i] - m);
    g_ex[g][i] = v;
    atomicAdd(&g_segsum[g][d * Hh + h], v);
}

// ---------------- fused aggregation + label propagation (warp per edge) ----------------
__global__ void k_agg(const int* __restrict__ src, const int* __restrict__ dst,
                      const float* __restrict__ y, int g) {
    const int warp = threadIdx.x >> 5;
    const int lane = threadIdx.x & 31;
    const int e = blockIdx.x * (blockDim.x >> 5) + warp;
    if (e >= Ee) return;
    const int s = src[e];
    const int d = dst[e];
    float a = 0.f;
    if (lane < 4) a = g_ex[g][e * Hh + lane] / g_segsum[g][d * Hh + lane];
    const float A0 = __shfl_sync(0xFFFFFFFFu, a, 0);
    const float A1 = __shfl_sync(0xFFFFFFFFu, a, 1);
    const float A2 = __shfl_sync(0xFFFFFFFFu, a, 2);
    const float A3 = __shfl_sync(0xFFFFFFFFu, a, 3);
    const float am = 0.25f * (A0 + A1 + A2 + A3);

    // feature aggregation: ft[dst] += fs[src] * a_h ; lane handles 4 consecutive floats
    {
        const float ah = (lane < 8) ? A0 : (lane < 16) ? A1 : (lane < 24) ? A2 : A3;
        const float4 v = ((const float4*)(g_fs + s * INd))[lane];
        float* pa = g_acc + d * INd + lane * 4;
        red_add_v4(pa, v.x * ah, v.y * ah, v.z * ah, v.w * ah);
    }
    // label propagation: yh[dst] += y[src] * a_mean (512 floats)
    {
        const float4* py = (const float4*)(y + (size_t)s * Ll);
        float* pyh = g_yh + (size_t)d * Ll;
#pragma unroll
        for (int i = 0; i < 4; i++) {
            int j = i * 32 + lane;          // float4 index 0..127
            float4 v = py[j];
            red_add_v4(pyh + j * 4, v.x * am, v.y * am, v.z * am, v.w * am);
        }
    }
}

// ---------------- epilogue h: mean over heads + residual + elu ----------------
__global__ void k_h(const float* __restrict__ x, float* __restrict__ out) {
    int i = blockIdx.x * blockDim.x + threadIdx.x;
    if (i >= Nn * Ff) return;
    int n = i / Ff, f = i % Ff;
    float sum = 0.f;
#pragma unroll
    for (int h = 0; h < Hh; h++) {
        int idx = n * INd + h * Ff + f;
        sum += g_acc[idx] + 2.f * x[idx];
    }
    sum *= 0.25f;
    out[i] = sum > 0.f ? sum : expm1f(sum);
}

// ---------------- epilogue y: L2 normalize + flag select (warp per node) ----------------
__global__ void k_y(const float* __restrict__ y, const void* __restrict__ flag,
                    float* __restrict__ out) {
    const int warp = threadIdx.x >> 5;
    const int lane = threadIdx.x & 31;
    const int n = blockIdx.x * (blockDim.x >> 5) + warp;
    if (n >= Nn) return;
    const float4* pr = (const float4*)(g_yh + (size_t)n * Ll);
    float4 v[4];
    float ss = 0.f;
#pragma unroll
    for (int i = 0; i < 4; i++) {
        v[i] = pr[i * 32 + lane];
        ss += v[i].x * v[i].x + v[i].y * v[i].y + v[i].z * v[i].z + v[i].w * v[i].w;
    }
#pragma unroll
    for (int o = 16; o; o >>= 1) ss += __shfl_xor_sync(0xFFFFFFFFu, ss, o);
    const float inv = 1.f / fmaxf(sqrtf(ss), 1e-12f);

    bool f;
    int fmt = g_flag_fmt;
    if (fmt == 0)      f = ((const int*)flag)[n] != 0;
    else if (fmt == 1) f = ((const unsigned char*)flag)[n] != 0;
    else               f = ((const float*)flag)[n] != 0.f;

    float4* po = (float4*)(out + (size_t)Nn * Ff + (size_t)n * Ll);
    if (f) {
        const float4* py = (const float4*)(y + (size_t)n * Ll);
#pragma unroll
        for (int i = 0; i < 4; i++) po[i * 32 + lane] = py[i * 32 + lane];
    } else {
#pragma unroll
        for (int i = 0; i < 4; i++) {
            float4 w = v[i];
            w.x *= inv; w.y *= inv; w.z *= inv; w.w *= inv;
            po[i * 32 + lane] = w;
        }
    }
}

// ---------------- launch ----------------
extern "C" void kernel_launch(void* const* d_in, const int* in_sizes, int n_in,
                              void* d_out, int out_size) {
    const float* x     = (const float*)d_in[0];
    const float* y     = (const float*)d_in[1];
    const float* Ws    = (const float*)d_in[2];
    const float* bs    = (const float*)d_in[3];
    const float* Wd    = (const float*)d_in[4];
    const float* bd    = (const float*)d_in[5];
    const float* attn  = (const float*)d_in[6];
    const int*   src_p = (const int*)d_in[7];
    const int*   dst_p = (const int*)d_in[8];
    const int*   src_s = (const int*)d_in[9];
    const int*   dst_s = (const int*)d_in[10];
    const void*  dflag = d_in[11];
    float* out = (float*)d_out;

    k_flagfmt<<<1, 256>>>((const unsigned*)dflag);
    k_init<<<4096, 256>>>();
    k_proj<<<Nn / BR, 128>>>(x, Ws, bs, Wd, bd);

    const int warps_per_blk = 8;
    const int eblocks = (Ee + warps_per_blk - 1) / warps_per_blk;

    // graph p (g=0)
    k_logits<<<eblocks, 256>>>(src_p, dst_p, attn, 0);
    k_exp<<<(Ee * Hh + 255) / 256, 256>>>(dst_p, 0);
    k_agg<<<eblocks, 256>>>(src_p, dst_p, y, 0);

    // graph s (g=1)
    k_logits<<<eblocks, 256>>>(src_s, dst_s, attn, 1);
    k_exp<<<(Ee * Hh + 255) / 256, 256>>>(dst_s, 1);
    k_agg<<<eblocks, 256>>>(src_s, dst_s, y, 1);

    k_h<<<(Nn * Ff + 255) / 256, 256>>>(x, out);
    k_y<<<(Nn + 7) / 8, 256>>>(y, dflag, out);
}

// round 3
// speedup vs baseline: 1.4839x; 1.4839x over previous
#include <cuda_runtime.h>

#define Nn 50000
#define INd 128
#define Hh 4
#define Ff 32
#define Ee 500000
#define Ll 512
#define SLOPE 0.2f

// ---------------- device scratch (static, allocation-free) ----------------
__device__ __align__(16) float    g_fs[Nn * INd];          // feat_src (N,128)
__device__ __align__(16) float    g_fd[Nn * INd];          // feat_dst (N,128)
__device__ __align__(16) float    g_ex[2][Ee * Hh];        // logits -> exp -> normalized a
__device__               float    g_am[2][Ee];             // head-mean attention per edge
__device__ __align__(16) unsigned g_segmax[2][Nn * Hh];    // encoded-float max
__device__ __align__(16) float    g_segsum[2][Nn * Hh];    // softmax denom
__device__               int      g_cnt[2][Nn];            // in-degree histogram
__device__               int      g_off[2][Nn + 1];        // CSR offsets
__device__               int      g_cur[2][Nn];            // fill cursors
__device__               int      g_csr[2][Ee];            // edge ids grouped by dst
__device__               int      g_flag_fmt;              // 0=int32, 1=uint8, 2=float32

// orderable-uint encoding of float for atomicMax
__device__ __forceinline__ unsigned encf(float f) {
    unsigned u = __float_as_uint(f);
    return (u & 0x80000000u) ? ~u : (u | 0x80000000u);
}
__device__ __forceinline__ float decf(unsigned u) {
    return (u & 0x80000000u) ? __uint_as_float(u ^ 0x80000000u)
                             : __uint_as_float(~u);
}

// ---------------- flag format detection (single block, deterministic) ----------------
__global__ void k_flagfmt(const unsigned* __restrict__ p) {
    __shared__ int s_word_not01, s_byte_not01;
    if (threadIdx.x == 0) { s_word_not01 = 0; s_byte_not01 = 0; }
    __syncthreads();
    const int nwords = Nn / 4;
    int w_bad = 0, b_bad = 0;
    for (int i = threadIdx.x; i < nwords; i += blockDim.x) {
        unsigned w = p[i];
        if (w > 1u) w_bad = 1;
        unsigned b0 = w & 0xFFu, b1 = (w >> 8) & 0xFFu, b2 = (w >> 16) & 0xFFu, b3 = (w >> 24) & 0xFFu;
        if (b0 > 1u || b1 > 1u || b2 > 1u || b3 > 1u) b_bad = 1;
    }
    if (w_bad) atomicOr(&s_word_not01, 1);
    if (b_bad) atomicOr(&s_byte_not01, 1);
    __syncthreads();
    if (threadIdx.x == 0) {
        int fmt;
        if (!s_word_not01) fmt = 0;
        else if (!s_byte_not01) fmt = 1;
        else fmt = 2;
        g_flag_fmt = fmt;
    }
}

// ---------------- init: zero softmax state + histograms ----------------
__global__ void k_init() {
    int tid = blockIdx.x * blockDim.x + threadIdx.x;
    int stride = gridDim.x * blockDim.x;
    unsigned* sm = (unsigned*)g_segmax;
    float* ss = (float*)g_segsum;
    const int nseg = 2 * Nn * Hh;
    for (int i = tid; i < nseg; i += stride) { sm[i] = 0u; ss[i] = 0.f; }
    int* cnt = (int*)g_cnt;
    for (int i = tid; i < 2 * Nn; i += stride) cnt[i] = 0;
}

// ---------------- projection: fs = x W_src^T + b_src ; fd likewise ----------------
#define BR 16
__global__ void k_proj(const float* __restrict__ x,
                       const float* __restrict__ Ws, const float* __restrict__ bs,
                       const float* __restrict__ Wd, const float* __restrict__ bd) {
    __shared__ float xs[BR][INd];
    const int row0 = blockIdx.x * BR;
    for (int i = threadIdx.x; i < BR * INd; i += blockDim.x) {
        int r = i / INd, c = i % INd;
        xs[r][c] = x[(row0 + r) * INd + c];
    }
    __syncthreads();
    const int col = threadIdx.x;
    float accS[BR], accD[BR];
#pragma unroll
    for (int r = 0; r < BR; r++) { accS[r] = 0.f; accD[r] = 0.f; }
    const float* wsr = Ws + col * INd;
    const float* wdr = Wd + col * INd;
    for (int k = 0; k < INd; k++) {
        float ws = __ldg(wsr + k);
        float wd = __ldg(wdr + k);
#pragma unroll
        for (int r = 0; r < BR; r++) {
            float xv = xs[r][k];
            accS[r] += xv * ws;
            accD[r] += xv * wd;
        }
    }
    float bsv = bs[col], bdv = bd[col];
#pragma unroll
    for (int r = 0; r < BR; r++) {
        g_fs[(row0 + r) * INd + col] = accS[r] + bsv;
        g_fd[(row0 + r) * INd + col] = accD[r] + bdv;
    }
}

// ---------------- CSR build: histogram -> scan -> fill ----------------
__global__ void k_hist(const int* __restrict__ dst, int g) {
    int e = blockIdx.x * blockDim.x + threadIdx.x;
    if (e < Ee) atomicAdd(&g_cnt[g][dst[e]], 1);
}

__global__ void k_scan() {  // grid = 2 (one block per graph), 1024 threads
    const int g = blockIdx.x;
    const int t = threadIdx.x;
    const int lane = t & 31, w = t >> 5;
    __shared__ int wsum[32];
    __shared__ int s_carry;
    if (t == 0) { g_off[g][0] = 0; s_carry = 0; }
    __syncthreads();
    for (int base = 0; base < Nn; base += 1024) {
        int i = base + t;
        int c0 = (i < Nn) ? g_cnt[g][i] : 0;
        int v = c0;
#pragma unroll
        for (int o = 1; o < 32; o <<= 1) {
            int u = __shfl_up_sync(0xFFFFFFFFu, v, o);
            if (lane >= o) v += u;
        }
        if (lane == 31) wsum[w] = v;
        __syncthreads();
        if (w == 0) {
            int sv = wsum[lane];
#pragma unroll
            for (int o = 1; o < 32; o <<= 1) {
                int u = __shfl_up_sync(0xFFFFFFFFu, sv, o);
                if (lane >= o) sv += u;
            }
            wsum[lane] = sv;
        }
        __syncthreads();
        int add = (w > 0) ? wsum[w - 1] : 0;
        int incl = v + add + s_carry;
        if (i < Nn) {
            g_off[g][i + 1] = incl;
            g_cur[g][i] = incl - c0;   // exclusive prefix = list start
        }
        __syncthreads();
        if (t == 1023) s_carry = incl;
        __syncthreads();
    }
}

__global__ void k_fill(const int* __restrict__ dst, int g) {
    int e = blockIdx.x * blockDim.x + threadIdx.x;
    if (e >= Ee) return;
    int pos = atomicAdd(&g_cur[g][dst[e]], 1);
    g_csr[g][pos] = e;
}

// ---------------- edge logits + segment max (warp per edge, float4) ----------------
__global__ void k_logits(const int* __restrict__ src, const int* __restrict__ dst,
                         const float* __restrict__ attn, int g) {
    const int warp = threadIdx.x >> 5;
    const int lane = threadIdx.x & 31;
    const int e = blockIdx.x * (blockDim.x >> 5) + warp;
    if (e >= Ee) return;
    const int s = src[e];
    const int d = dst[e];
    const float4 fs4 = __ldg(((const float4*)g_fs) + s * 32 + lane);
    const float4 fd4 = __ldg(((const float4*)g_fd) + d * 32 + lane);
    const float4 at  = __ldg(((const float4*)attn) + lane);
    float v, p;
    v = fs4.x + fd4.x; v = v > 0.f ? v : SLOPE * v; p  = v * at.x;
    v = fs4.y + fd4.y; v = v > 0.f ? v : SLOPE * v; p += v * at.y;
    v = fs4.z + fd4.z; v = v > 0.f ? v : SLOPE * v; p += v * at.z;
    v = fs4.w + fd4.w; v = v > 0.f ? v : SLOPE * v; p += v * at.w;
    // reduce within each 8-lane group (one head per group)
    p += __shfl_xor_sync(0xFFFFFFFFu, p, 4);
    p += __shfl_xor_sync(0xFFFFFFFFu, p, 2);
    p += __shfl_xor_sync(0xFFFFFFFFu, p, 1);
    if ((lane & 7) == 0) {
        int h = lane >> 3;
        g_ex[g][e * Hh + h] = p;
        atomicMax(&g_segmax[g][d * Hh + h], encf(p));
    }
}

// ---------------- exp + segment sum ----------------
__global__ void k_exp(const int* __restrict__ dst, int g) {
    int i = blockIdx.x * blockDim.x + threadIdx.x;
    if (i >= Ee * Hh) return;
    int e = i >> 2;
    int h = i & 3;
    int d = dst[e];
    float m = decf(g_segmax[g][d * Hh + h]);
    float v = expf(g_ex[g][i] - m);
    g_ex[g][i] = v;
    atomicAdd(&g_segsum[g][d * Hh + h], v);
}

// ---------------- normalize: a = ex / segsum[dst] (in place) + head mean ----------------
__global__ void k_norm(const int* __restrict__ dst, int g) {
    int e = blockIdx.x * blockDim.x + threadIdx.x;
    if (e >= Ee) return;
    int d = dst[e];
    float4 ex = ((const float4*)g_ex[g])[e];
    float4 sv = __ldg(((const float4*)g_segsum[g]) + d);
    float4 a;
    a.x = ex.x / sv.x; a.y = ex.y / sv.y; a.z = ex.z / sv.z; a.w = ex.w / sv.w;
    ((float4*)g_ex[g])[e] = a;
    g_am[g][e] = 0.25f * (a.x + a.y + a.z + a.w);
}

// ---------------- fused gather: per-dst aggregation + both epilogues ----------------
__global__ void __launch_bounds__(256) k_gather(
        const float* __restrict__ x, const float* __restrict__ y,
        const int* __restrict__ src_p, const int* __restrict__ src_s,
        const void* __restrict__ flag, float* __restrict__ out) {
    const int warp = threadIdx.x >> 5;
    const int lane = threadIdx.x & 31;
    const int n = blockIdx.x * (blockDim.x >> 5) + warp;
    if (n >= Nn) return;

    // acc covers this node's 128 projected floats: lane l -> floats 4l..4l+3
    float4 acc = __ldg(((const float4*)x) + n * 32 + lane);
    acc.x *= 2.f; acc.y *= 2.f; acc.z *= 2.f; acc.w *= 2.f;
    // yh: lane l -> float4 indices l, l+32, l+64, l+96 of the 512-vector
    float4 yh[4];
#pragma unroll
    for (int i = 0; i < 4; i++) yh[i] = make_float4(0.f, 0.f, 0.f, 0.f);

#pragma unroll
    for (int g = 0; g < 2; g++) {
        const int* srcarr = g ? src_s : src_p;
        const int beg = g_off[g][n];
        const int end = g_off[g][n + 1];
        for (int k = beg; k < end; k++) {
            const int e = g_csr[g][k];
            const int s = __ldg(srcarr + e);
            const float am = __ldg(&g_am[g][e]);
            const float ah = __ldg(&g_ex[g][e * Hh + (lane >> 3)]);  // head = lane/8
            const float4 fv = __ldg(((const float4*)g_fs) + s * 32 + lane);
            acc.x += fv.x * ah; acc.y += fv.y * ah;
            acc.z += fv.z * ah; acc.w += fv.w * ah;
            const float4* py = ((const float4*)y) + (size_t)s * 128;
#pragma unroll
            for (int i = 0; i < 4; i++) {
                const float4 v = __ldg(py + i * 32 + lane);
                yh[i].x += v.x * am; yh[i].y += v.y * am;
                yh[i].z += v.z * am; yh[i].w += v.w * am;
            }
        }
    }

    // ---- epilogue h: mean over heads + elu; heads of float f live in lanes {f/4, +8, +16, +24}
#pragma unroll
    for (int o = 8; o <= 16; o <<= 1) {
        acc.x += __shfl_xor_sync(0xFFFFFFFFu, acc.x, o);
        acc.y += __shfl_xor_sync(0xFFFFFFFFu, acc.y, o);
        acc.z += __shfl_xor_sync(0xFFFFFFFFu, acc.z, o);
        acc.w += __shfl_xor_sync(0xFFFFFFFFu, acc.w, o);
    }
    if (lane < 8) {
        float4 r;
        r.x = acc.x * 0.25f; r.y = acc.y * 0.25f; r.z = acc.z * 0.25f; r.w = acc.w * 0.25f;
        r.x = r.x > 0.f ? r.x : expm1f(r.x);
        r.y = r.y > 0.f ? r.y : expm1f(r.y);
        r.z = r.z > 0.f ? r.z : expm1f(r.z);
        r.w = r.w > 0.f ? r.w : expm1f(r.w);
        ((float4*)out)[n * 8 + lane] = r;
    }

    // ---- epilogue y: L2 normalize or passthrough per flag
    float ssq = 0.f;
#pragma unroll
    for (int i = 0; i < 4; i++)
        ssq += yh[i].x * yh[i].x + yh[i].y * yh[i].y + yh[i].z * yh[i].z + yh[i].w * yh[i].w;
#pragma unroll
    for (int o = 16; o; o >>= 1) ssq += __shfl_xor_sync(0xFFFFFFFFu, ssq, o);
    const float inv = 1.f / fmaxf(sqrtf(ssq), 1e-12f);

    bool f;
    const int fmt = g_flag_fmt;
    if (fmt == 0)      f = ((const int*)flag)[n] != 0;
    else if (fmt == 1) f = ((const unsigned char*)flag)[n] != 0;
    else               f = ((const float*)flag)[n] != 0.f;

    float4* po = (float4*)(out + (size_t)Nn * Ff) + (size_t)n * 128;
    if (f) {
        const float4* py = ((const float4*)y) + (size_t)n * 128;
#pragma unroll
        for (int i = 0; i < 4; i++) po[i * 32 + lane] = __ldg(py + i * 32 + lane);
    } else {
#pragma unroll
        for (int i = 0; i < 4; i++) {
            float4 w = yh[i];
            w.x *= inv; w.y *= inv; w.z *= inv; w.w *= inv;
            po[i * 32 + lane] = w;
        }
    }
}

// ---------------- launch ----------------
extern "C" void kernel_launch(void* const* d_in, const int* in_sizes, int n_in,
                              void* d_out, int out_size) {
    const float* x     = (const float*)d_in[0];
    const float* y     = (const float*)d_in[1];
    const float* Ws    = (const float*)d_in[2];
    const float* bs    = (const float*)d_in[3];
    const float* Wd    = (const float*)d_in[4];
    const float* bd    = (const float*)d_in[5];
    const float* attn  = (const float*)d_in[6];
    const int*   src_p = (const int*)d_in[7];
    const int*   dst_p = (const int*)d_in[8];
    const int*   src_s = (const int*)d_in[9];
    const int*   dst_s = (const int*)d_in[10];
    const void*  dflag = d_in[11];
    float* out = (float*)d_out;

    const int et = (Ee + 255) / 256;           // thread-per-edge blocks
    const int ew = (Ee + 7) / 8;               // warp-per-edge blocks (256 thr)

    k_flagfmt<<<1, 256>>>((const unsigned*)dflag);
    k_init<<<256, 256>>>();
    k_proj<<<Nn / BR, 128>>>(x, Ws, bs, Wd, bd);

    // CSR build (both graphs)
    k_hist<<<et, 256>>>(dst_p, 0);
    k_hist<<<et, 256>>>(dst_s, 1);
    k_scan<<<2, 1024>>>();
    k_fill<<<et, 256>>>(dst_p, 0);
    k_fill<<<et, 256>>>(dst_s, 1);

    // edge softmax (both graphs)
    k_logits<<<ew, 256>>>(src_p, dst_p, attn, 0);
    k_exp<<<(Ee * Hh + 255) / 256, 256>>>(dst_p, 0);
    k_norm<<<et, 256>>>(dst_p, 0);
    k_logits<<<ew, 256>>>(src_s, dst_s, attn, 1);
    k_exp<<<(Ee * Hh + 255) / 256, 256>>>(dst_s, 1);
    k_norm<<<et, 256>>>(dst_s, 1);

    // fused aggregation + epilogues
    k_gather<<<(Nn + 7) / 8, 256>>>(x, y, src_p, src_s, dflag, out);
}